// round 1
// baseline (speedup 1.0000x reference)
#include <cuda_runtime.h>
#include <cstdint>

// Problem dims (fixed by the dataset)
#define S_TOK 8192      // B*T
#define MDIM  1024
#define HDIM  4096
#define ODIM  1024
#define EEXP  4
#define CCAP  2048      // ceil(S/E)

// ---------------- device scratch (no cudaMalloc allowed) ----------------
__device__ float g_disp [(size_t)EEXP * CCAP * MDIM];   // 32 MB  dispatched tokens
__device__ float g_h    [(size_t)EEXP * CCAP * HDIM];   // 128 MB fc1 activations
__device__ float g_eout [(size_t)EEXP * CCAP * ODIM];   // 32 MB  fc2 outputs
__device__ float g_probs[S_TOK * 4];                    // softmax probs per token
__device__ float g_gate [S_TOK];                        // gate value of argmax expert
__device__ int   g_eidx [S_TOK];                        // argmax expert per token
__device__ int   g_tok_slot[S_TOK];                     // token -> e*C+slot or -1
__device__ int   g_slot_tok[EEXP * CCAP];               // slot  -> token or -1

// ---------------- helpers ----------------
__device__ __forceinline__ float to_tf32(float x) {
    uint32_t u;
    asm volatile("cvt.rna.tf32.f32 %0, %1;" : "=r"(u) : "f"(x));
    return __uint_as_float(u);
}

__device__ __forceinline__ float gelu_tanh(float x) {
    // jax.nn.gelu(approximate=True)
    float x3 = x * x * x;
    return 0.5f * x * (1.0f + tanhf(0.7978845608028654f * (x + 0.044715f * x3)));
}

// ---------------- 1. gate: logits -> softmax/argmax/probs ----------------
// one warp per token; gate_w is [M, 4] so a float4 per m gives all experts.
__global__ void gate_kernel(const float* __restrict__ feats,
                            const float* __restrict__ gw) {
    int gtid = blockIdx.x * blockDim.x + threadIdx.x;
    int tok  = gtid >> 5;
    int lane = threadIdx.x & 31;
    if (tok >= S_TOK) return;

    const float* f = feats + (size_t)tok * MDIM;
    float a0 = 0.f, a1 = 0.f, a2 = 0.f, a3 = 0.f;
    for (int m = lane; m < MDIM; m += 32) {
        float fv = f[m];
        float4 w = __ldg((const float4*)gw + m);
        a0 += fv * w.x; a1 += fv * w.y; a2 += fv * w.z; a3 += fv * w.w;
    }
    #pragma unroll
    for (int o = 16; o; o >>= 1) {
        a0 += __shfl_down_sync(0xffffffffu, a0, o);
        a1 += __shfl_down_sync(0xffffffffu, a1, o);
        a2 += __shfl_down_sync(0xffffffffu, a2, o);
        a3 += __shfl_down_sync(0xffffffffu, a3, o);
    }
    if (lane == 0) {
        float l[4] = {a0, a1, a2, a3};
        float mx = l[0]; int ai = 0;
        #pragma unroll
        for (int e = 1; e < 4; e++) if (l[e] > mx) { mx = l[e]; ai = e; }  // first-max like jnp.argmax
        float p[4], s = 0.f;
        #pragma unroll
        for (int e = 0; e < 4; e++) { p[e] = expf(l[e] - mx); s += p[e]; }
        float inv = 1.0f / s;
        ((float4*)g_probs)[tok] = make_float4(p[0]*inv, p[1]*inv, p[2]*inv, p[3]*inv);
        g_eidx[tok] = ai;
        g_gate[tok] = p[ai] * inv;
    }
}

// ---------------- 2. capacity scan (must replicate token-order cumsum) ----
// single CTA, 1024 threads * 8 tokens. 4 counters packed 16b each into u64.
__global__ void scan_kernel() {
    __shared__ unsigned long long sc[1024];
    int tid = threadIdx.x;

    for (int i = tid; i < EEXP * CCAP; i += 1024) g_slot_tok[i] = -1;

    int el[8];
    unsigned long long cnt = 0ull;
    #pragma unroll
    for (int j = 0; j < 8; j++) {
        int e = g_eidx[tid * 8 + j];
        el[j] = e;
        cnt += 1ull << (e * 16);
    }
    sc[tid] = cnt;
    __syncthreads();
    for (int off = 1; off < 1024; off <<= 1) {
        unsigned long long v = 0ull;
        if (tid >= off) v = sc[tid - off];
        __syncthreads();
        sc[tid] += v;
        __syncthreads();
    }
    unsigned long long base = sc[tid] - cnt;  // exclusive prefix for this thread
    #pragma unroll
    for (int j = 0; j < 8; j++) {
        int e   = el[j];
        int pos = (int)((base >> (e * 16)) & 0xFFFFull);
        int tok = tid * 8 + j;
        if (pos < CCAP) {
            int slot = e * CCAP + pos;
            g_tok_slot[tok]  = slot;
            g_slot_tok[slot] = tok;
        } else {
            g_tok_slot[tok] = -1;   // overflow: dropped
        }
        base += 1ull << (e * 16);
    }
}

// ---------------- 3. gather tokens into dispatched [E*C, M] ----------------
__global__ void gather_kernel(const float* __restrict__ feats) {
    int slot = blockIdx.x;
    int t    = threadIdx.x;           // 256 threads, one float4 each (M=1024)
    int tok  = g_slot_tok[slot];
    float4* d = (float4*)(g_disp + (size_t)slot * MDIM);
    if (tok < 0) {
        d[t] = make_float4(0.f, 0.f, 0.f, 0.f);
    } else {
        d[t] = ((const float4*)(feats + (size_t)tok * MDIM))[t];
    }
}

// ---------------- 4/5. grouped GEMM (tf32 mma.sync), bias (+gelu) ----------
// PHASE1: g_disp[2048,1024] @ w1[1024,4096] -> gelu -> g_h
// else  : g_h  [2048,4096] @ w2[4096,1024] ->          g_eout
template <bool PHASE1>
__global__ void __launch_bounds__(256) moe_gemm(const float* __restrict__ Ball,
                                                const float* __restrict__ biasAll) {
    constexpr int K  = PHASE1 ? MDIM : HDIM;
    constexpr int N  = PHASE1 ? HDIM : ODIM;
    constexpr int BM = 128, BN = 128, BK = 32;

    const float* Aall = PHASE1 ? g_disp : g_h;
    float*       Call = PHASE1 ? g_h    : g_eout;

    const int e = blockIdx.z;
    const float* A    = Aall   + (size_t)e * CCAP * K;
    const float* B    = Ball   + (size_t)e * K * N;
    const float* bias = biasAll + (size_t)e * N;
    float*       C    = Call   + (size_t)e * CCAP * N;

    __shared__ float As[BK][BM + 5];   // +5 pad: conflict-free scattered STS
    __shared__ float Bs[BK][BN + 4];   // +4 pad: keeps 16B alignment for STS.128

    const int tid  = threadIdx.x;
    const int warp = tid >> 5, lane = tid & 31;
    const int wm = warp >> 2, wn = warp & 3;      // 2x4 warp grid, warp tile 64x32
    const int g  = lane >> 2, tg = lane & 3;
    const int rowBase = blockIdx.y * BM;
    const int colBase = blockIdx.x * BN;

    float acc[4][4][4];
    #pragma unroll
    for (int i = 0; i < 4; i++)
        #pragma unroll
        for (int j = 0; j < 4; j++)
            #pragma unroll
            for (int r = 0; r < 4; r++) acc[i][j][r] = 0.f;

    const float* Arow = A + (size_t)rowBase * K;

    for (int k0 = 0; k0 < K; k0 += BK) {
        // load A tile 128x32 (rows are K-contiguous), convert to tf32 at store
        #pragma unroll
        for (int i = 0; i < 4; i++) {
            int idx = tid + i * 256;
            int r = idx >> 3, kv = (idx & 7) * 4;
            float4 v = *(const float4*)(Arow + (size_t)r * K + k0 + kv);
            As[kv + 0][r] = to_tf32(v.x);
            As[kv + 1][r] = to_tf32(v.y);
            As[kv + 2][r] = to_tf32(v.z);
            As[kv + 3][r] = to_tf32(v.w);
        }
        // load B tile 32x128
        #pragma unroll
        for (int i = 0; i < 4; i++) {
            int idx = tid + i * 256;
            int kr = idx >> 5, nv = (idx & 31) * 4;
            float4 v = *(const float4*)(B + (size_t)(k0 + kr) * N + colBase + nv);
            v.x = to_tf32(v.x); v.y = to_tf32(v.y);
            v.z = to_tf32(v.z); v.w = to_tf32(v.w);
            *(float4*)&Bs[kr][nv] = v;
        }
        __syncthreads();

        #pragma unroll
        for (int ks = 0; ks < 4; ks++) {
            const int kk = ks * 8;
            uint32_t af[4][4], bf[4][2];
            #pragma unroll
            for (int mt = 0; mt < 4; mt++) {
                int m = wm * 64 + mt * 16 + g;
                af[mt][0] = __float_as_uint(As[kk + tg    ][m]);
                af[mt][1] = __float_as_uint(As[kk + tg    ][m + 8]);
                af[mt][2] = __float_as_uint(As[kk + tg + 4][m]);
                af[mt][3] = __float_as_uint(As[kk + tg + 4][m + 8]);
            }
            #pragma unroll
            for (int nt = 0; nt < 4; nt++) {
                int n = wn * 32 + nt * 8 + g;
                bf[nt][0] = __float_as_uint(Bs[kk + tg    ][n]);
                bf[nt][1] = __float_as_uint(Bs[kk + tg + 4][n]);
            }
            #pragma unroll
            for (int mt = 0; mt < 4; mt++)
                #pragma unroll
                for (int nt = 0; nt < 4; nt++) {
                    asm volatile(
                        "mma.sync.aligned.m16n8k8.row.col.f32.tf32.tf32.f32 "
                        "{%0,%1,%2,%3}, {%4,%5,%6,%7}, {%8,%9}, {%0,%1,%2,%3};\n"
                        : "+f"(acc[mt][nt][0]), "+f"(acc[mt][nt][1]),
                          "+f"(acc[mt][nt][2]), "+f"(acc[mt][nt][3])
                        : "r"(af[mt][0]), "r"(af[mt][1]), "r"(af[mt][2]), "r"(af[mt][3]),
                          "r"(bf[nt][0]), "r"(bf[nt][1]));
                }
        }
        __syncthreads();
    }

    // epilogue: bias (+gelu), float2 stores (c0,c1 are adjacent columns)
    #pragma unroll
    for (int mt = 0; mt < 4; mt++) {
        int r0 = rowBase + wm * 64 + mt * 16 + g;
        #pragma unroll
        for (int nt = 0; nt < 4; nt++) {
            int c0 = colBase + wn * 32 + nt * 8 + tg * 2;
            float b0 = __ldg(bias + c0), b1 = __ldg(bias + c0 + 1);
            float v0 = acc[mt][nt][0] + b0, v1 = acc[mt][nt][1] + b1;
            float v2 = acc[mt][nt][2] + b0, v3 = acc[mt][nt][3] + b1;
            if (PHASE1) {
                v0 = gelu_tanh(v0); v1 = gelu_tanh(v1);
                v2 = gelu_tanh(v2); v3 = gelu_tanh(v3);
            }
            *(float2*)&C[(size_t)r0       * N + c0] = make_float2(v0, v1);
            *(float2*)&C[(size_t)(r0 + 8) * N + c0] = make_float2(v2, v3);
        }
    }
}

// ---------------- 6. combine: out[s] = gate[s] * expert_out[slot] ----------
__global__ void combine_kernel(float* __restrict__ out) {
    int s = blockIdx.x;
    int t = threadIdx.x;                 // 256 threads, one float4 each (O=1024)
    int slot = g_tok_slot[s];
    float4* o = (float4*)(out + (size_t)s * ODIM);
    if (slot < 0) {
        o[t] = make_float4(0.f, 0.f, 0.f, 0.f);
        return;
    }
    float gv = g_gate[s];
    float4 v = ((const float4*)(g_eout + (size_t)slot * ODIM))[t];
    v.x *= gv; v.y *= gv; v.z *= gv; v.w *= gv;
    o[t] = v;
}

// ---------------- 7. l_aux (deterministic tree reduction) ----------------
__global__ void laux_kernel(float* __restrict__ out, int out_size) {
    __shared__ float sp[4][256];
    __shared__ float sc[4][256];
    int t = threadIdx.x;
    float p[4] = {0.f, 0.f, 0.f, 0.f};
    float c[4] = {0.f, 0.f, 0.f, 0.f};
    for (int s = t; s < S_TOK; s += 256) {
        float4 pr = ((const float4*)g_probs)[s];
        p[0] += pr.x; p[1] += pr.y; p[2] += pr.z; p[3] += pr.w;
        int e = g_eidx[s];
        #pragma unroll
        for (int k = 0; k < 4; k++) c[k] += (e == k) ? 1.f : 0.f;
    }
    #pragma unroll
    for (int k = 0; k < 4; k++) { sp[k][t] = p[k]; sc[k][t] = c[k]; }
    __syncthreads();
    for (int off = 128; off; off >>= 1) {
        if (t < off) {
            #pragma unroll
            for (int k = 0; k < 4; k++) {
                sp[k][t] += sp[k][t + off];
                sc[k][t] += sc[k][t + off];
            }
        }
        __syncthreads();
    }
    if (t == 0 && out_size > S_TOK * ODIM) {
        float inv = 1.0f / (float)S_TOK;
        float l = 0.f;
        #pragma unroll
        for (int k = 0; k < 4; k++) l += (sp[k][0] * inv) * (sc[k][0] * inv);
        out[(size_t)S_TOK * ODIM] = l * (float)EEXP;
    }
}

// ---------------- launch ----------------
extern "C" void kernel_launch(void* const* d_in, const int* in_sizes, int n_in,
                              void* d_out, int out_size) {
    (void)in_sizes; (void)n_in;
    const float* hs = (const float*)d_in[0];   // [8,1024,1024]
    const float* gw = (const float*)d_in[1];   // [1024,4]
    const float* w1 = (const float*)d_in[2];   // [4,1024,4096]
    const float* b1 = (const float*)d_in[3];   // [4,4096]
    const float* w2 = (const float*)d_in[4];   // [4,4096,1024]
    const float* b2 = (const float*)d_in[5];   // [4,1024]
    float* out = (float*)d_out;

    gate_kernel<<<S_TOK / 8, 256>>>(hs, gw);
    scan_kernel<<<1, 1024>>>();
    gather_kernel<<<EEXP * CCAP, 256>>>(hs);
    moe_gemm<true ><<<dim3(HDIM / 128, CCAP / 128, EEXP), 256>>>(w1, b1);
    moe_gemm<false><<<dim3(ODIM / 128, CCAP / 128, EEXP), 256>>>(w2, b2);
    combine_kernel<<<S_TOK, 256>>>(out);
    laux_kernel<<<1, 256>>>(out, out_size);
}

// round 3
// speedup vs baseline: 1.3796x; 1.3796x over previous
#include <cuda_runtime.h>
#include <cstdint>

// Problem dims (fixed by the dataset)
#define S_TOK 8192      // B*T
#define MDIM  1024
#define HDIM  4096
#define ODIM  1024
#define EEXP  4
#define CCAP  2048      // ceil(S/E)

// ---------------- device scratch (no cudaMalloc allowed) ----------------
__device__ float g_disp [(size_t)EEXP * CCAP * MDIM];   // 32 MB  dispatched tokens (tf32)
__device__ float g_h    [(size_t)EEXP * CCAP * HDIM];   // 128 MB fc1 activations (tf32)
__device__ float g_eout [(size_t)EEXP * CCAP * ODIM];   // 32 MB  fc2 outputs
__device__ float g_w1r  [(size_t)EEXP * MDIM * HDIM];   // 64 MB  w1 rounded to tf32
__device__ float g_w2r  [(size_t)EEXP * HDIM * ODIM];   // 64 MB  w2 rounded to tf32
__device__ float g_probs[S_TOK * 4];
__device__ float g_gate [S_TOK];
__device__ int   g_eidx [S_TOK];
__device__ int   g_tok_slot[S_TOK];
__device__ int   g_slot_tok[EEXP * CCAP];

// ---------------- helpers ----------------
__device__ __forceinline__ float to_tf32(float x) {
    uint32_t u;
    asm volatile("cvt.rna.tf32.f32 %0, %1;" : "=r"(u) : "f"(x));
    return __uint_as_float(u);
}

__device__ __forceinline__ float gelu_tanh(float x) {
    float x3 = x * x * x;
    return 0.5f * x * (1.0f + tanhf(0.7978845608028654f * (x + 0.044715f * x3)));
}

__device__ __forceinline__ uint32_t smem_u32(const void* p) {
    uint32_t a;
    asm("{ .reg .u64 t; cvta.to.shared.u64 t, %1; cvt.u32.u64 %0, t; }" : "=r"(a) : "l"(p));
    return a;
}

__device__ __forceinline__ void cp16(uint32_t s, const void* g) {
    asm volatile("cp.async.cg.shared.global [%0], [%1], 16;\n" :: "r"(s), "l"(g));
}
__device__ __forceinline__ void cp_commit() {
    asm volatile("cp.async.commit_group;\n" ::: "memory");
}
template<int N> __device__ __forceinline__ void cp_wait() {
    asm volatile("cp.async.wait_group %0;\n" :: "n"(N) : "memory");
}

// ---------------- 1. gate ----------------
__global__ void gate_kernel(const float* __restrict__ feats,
                            const float* __restrict__ gw) {
    int gtid = blockIdx.x * blockDim.x + threadIdx.x;
    int tok  = gtid >> 5;
    int lane = threadIdx.x & 31;
    if (tok >= S_TOK) return;

    const float* f = feats + (size_t)tok * MDIM;
    float a0 = 0.f, a1 = 0.f, a2 = 0.f, a3 = 0.f;
    for (int m = lane; m < MDIM; m += 32) {
        float fv = f[m];
        float4 w = __ldg((const float4*)gw + m);
        a0 += fv * w.x; a1 += fv * w.y; a2 += fv * w.z; a3 += fv * w.w;
    }
    #pragma unroll
    for (int o = 16; o; o >>= 1) {
        a0 += __shfl_down_sync(0xffffffffu, a0, o);
        a1 += __shfl_down_sync(0xffffffffu, a1, o);
        a2 += __shfl_down_sync(0xffffffffu, a2, o);
        a3 += __shfl_down_sync(0xffffffffu, a3, o);
    }
    if (lane == 0) {
        float l[4] = {a0, a1, a2, a3};
        float mx = l[0]; int ai = 0;
        #pragma unroll
        for (int e = 1; e < 4; e++) if (l[e] > mx) { mx = l[e]; ai = e; }
        float p[4], s = 0.f;
        #pragma unroll
        for (int e = 0; e < 4; e++) { p[e] = expf(l[e] - mx); s += p[e]; }
        float inv = 1.0f / s;
        ((float4*)g_probs)[tok] = make_float4(p[0]*inv, p[1]*inv, p[2]*inv, p[3]*inv);
        g_eidx[tok] = ai;
        g_gate[tok] = p[ai] * inv;
    }
}

// ---------------- 2. capacity scan ----------------
__global__ void scan_kernel() {
    __shared__ unsigned long long sc[1024];
    int tid = threadIdx.x;

    for (int i = tid; i < EEXP * CCAP; i += 1024) g_slot_tok[i] = -1;

    int el[8];
    unsigned long long cnt = 0ull;
    #pragma unroll
    for (int j = 0; j < 8; j++) {
        int e = g_eidx[tid * 8 + j];
        el[j] = e;
        cnt += 1ull << (e * 16);
    }
    sc[tid] = cnt;
    __syncthreads();
    for (int off = 1; off < 1024; off <<= 1) {
        unsigned long long v = 0ull;
        if (tid >= off) v = sc[tid - off];
        __syncthreads();
        sc[tid] += v;
        __syncthreads();
    }
    unsigned long long base = sc[tid] - cnt;
    #pragma unroll
    for (int j = 0; j < 8; j++) {
        int e   = el[j];
        int pos = (int)((base >> (e * 16)) & 0xFFFFull);
        int tok = tid * 8 + j;
        if (pos < CCAP) {
            int slot = e * CCAP + pos;
            g_tok_slot[tok]  = slot;
            g_slot_tok[slot] = tok;
        } else {
            g_tok_slot[tok] = -1;
        }
        base += 1ull << (e * 16);
    }
}

// ---------------- 3. gather (tf32-rounded) ----------------
__global__ void gather_kernel(const float* __restrict__ feats) {
    int slot = blockIdx.x;
    int t    = threadIdx.x;
    int tok  = g_slot_tok[slot];
    float4* d = (float4*)(g_disp + (size_t)slot * MDIM);
    if (tok < 0) {
        d[t] = make_float4(0.f, 0.f, 0.f, 0.f);
    } else {
        float4 v = ((const float4*)(feats + (size_t)tok * MDIM))[t];
        v.x = to_tf32(v.x); v.y = to_tf32(v.y);
        v.z = to_tf32(v.z); v.w = to_tf32(v.w);
        d[t] = v;
    }
}

// ---------------- 3b. round weights to tf32 (elementwise) ----------------
__global__ void round_kernel(const float* __restrict__ src, float* __restrict__ dst,
                             int n4) {
    int i = blockIdx.x * blockDim.x + threadIdx.x;
    if (i >= n4) return;
    float4 v = ((const float4*)src)[i];
    v.x = to_tf32(v.x); v.y = to_tf32(v.y);
    v.z = to_tf32(v.z); v.w = to_tf32(v.w);
    ((float4*)dst)[i] = v;
}

// ---------------- 4/5. grouped GEMM: tf32 mma.sync + 3-stage cp.async ------
// PHASE1: g_disp[2048,1024] @ w1[1024,4096] -> gelu -> g_h (tf32)
// else  : g_h  [2048,4096] @ w2[4096,1024] ->          g_eout
#define GBM 128
#define GBN 128
#define GBK 32
#define NSTAGE 3
#define SA_STRIDE 36                    // floats per A row (32 + pad 4), 144B (16B-mult)
#define SB_STRIDE 132                   // floats per B row (128 + pad 4), 528B (16B-mult)
#define SA_FLOATS (GBM * SA_STRIDE)     // 4608
#define SB_FLOATS (GBK * SB_STRIDE)     // 4224
#define SMEM_FLOATS (NSTAGE * (SA_FLOATS + SB_FLOATS))
#define SMEM_BYTES  (SMEM_FLOATS * 4)   // 105984 B

template <bool PHASE1>
__global__ void __launch_bounds__(256, 2) moe_gemm(const float* __restrict__ Ball,
                                                   const float* __restrict__ biasAll) {
    constexpr int K  = PHASE1 ? MDIM : HDIM;
    constexpr int N  = PHASE1 ? HDIM : ODIM;
    constexpr int KT = K / GBK;

    extern __shared__ float smem[];
    float* As = smem;                       // [NSTAGE][GBM][SA_STRIDE]
    float* Bs = smem + NSTAGE * SA_FLOATS;  // [NSTAGE][GBK][SB_STRIDE]

    const float* Aall = PHASE1 ? g_disp : g_h;
    float*       Call = PHASE1 ? g_h    : g_eout;

    const int e = blockIdx.z;
    const float* A    = Aall    + (size_t)e * CCAP * K;
    const float* B    = Ball    + (size_t)e * K * N;
    const float* bias = biasAll + (size_t)e * N;
    float*       C    = Call    + (size_t)e * CCAP * N;

    const int tid  = threadIdx.x;
    const int warp = tid >> 5, lane = tid & 31;
    const int wm = warp >> 2, wn = warp & 3;      // 2x4 warp grid, warp tile 64x32
    const int g  = lane >> 2, tg = lane & 3;
    const int rowBase = blockIdx.y * GBM;
    const int colBase = blockIdx.x * GBN;

    const float* Ag = A + (size_t)rowBase * K;
    const float* Bg = B + colBase;

    const uint32_t sb = smem_u32(smem);

    // thread's fixed load coordinates
    const int a_r  = tid >> 3;            // 0..31 (plus 32*i)
    const int a_kc = (tid & 7) * 4;       // 0,4,..28
    const int b_kr = tid >> 5;            // 0..7 (plus 8*i)
    const int b_nc = (tid & 31) * 4;      // 0..124

    auto load_tile = [&](int kt, int stage) {
        const int k0 = kt * GBK;
        uint32_t sA = sb + (stage * SA_FLOATS) * 4;
        uint32_t sB = sb + (NSTAGE * SA_FLOATS + stage * SB_FLOATS) * 4;
        #pragma unroll
        for (int i = 0; i < 4; i++) {
            int r = a_r + i * 32;
            cp16(sA + (r * SA_STRIDE + a_kc) * 4, Ag + (size_t)r * K + k0 + a_kc);
        }
        #pragma unroll
        for (int i = 0; i < 4; i++) {
            int kr = b_kr + i * 8;
            cp16(sB + (kr * SB_STRIDE + b_nc) * 4, Bg + (size_t)(k0 + kr) * N + b_nc);
        }
    };

    float acc[4][4][4];
    #pragma unroll
    for (int i = 0; i < 4; i++)
        #pragma unroll
        for (int j = 0; j < 4; j++)
            #pragma unroll
            for (int r = 0; r < 4; r++) acc[i][j][r] = 0.f;

    // prologue: stages 0,1
    load_tile(0, 0); cp_commit();
    load_tile(1, 1); cp_commit();

    for (int kt = 0; kt < KT; kt++) {
        const int stage = kt % NSTAGE;
        cp_wait<1>();          // tile kt resident (only the newest group may be pending)
        __syncthreads();

        const float* Ast = As + stage * SA_FLOATS;
        const float* Bst = Bs + stage * SB_FLOATS;

        #pragma unroll
        for (int ks = 0; ks < 4; ks++) {
            const int kk = ks * 8;
            uint32_t af[4][4], bf[4][2];
            #pragma unroll
            for (int mt = 0; mt < 4; mt++) {
                const float* ar = Ast + (size_t)(wm * 64 + mt * 16 + g) * SA_STRIDE + kk + tg;
                af[mt][0] = __float_as_uint(ar[0]);
                af[mt][1] = __float_as_uint(ar[8 * SA_STRIDE]);
                af[mt][2] = __float_as_uint(ar[4]);
                af[mt][3] = __float_as_uint(ar[8 * SA_STRIDE + 4]);
            }
            #pragma unroll
            for (int nt = 0; nt < 4; nt++) {
                int n = wn * 32 + nt * 8 + g;
                bf[nt][0] = __float_as_uint(Bst[(kk + tg) * SB_STRIDE + n]);
                bf[nt][1] = __float_as_uint(Bst[(kk + tg + 4) * SB_STRIDE + n]);
            }
            #pragma unroll
            for (int mt = 0; mt < 4; mt++)
                #pragma unroll
                for (int nt = 0; nt < 4; nt++) {
                    asm volatile(
                        "mma.sync.aligned.m16n8k8.row.col.f32.tf32.tf32.f32 "
                        "{%0,%1,%2,%3}, {%4,%5,%6,%7}, {%8,%9}, {%0,%1,%2,%3};\n"
                        : "+f"(acc[mt][nt][0]), "+f"(acc[mt][nt][1]),
                          "+f"(acc[mt][nt][2]), "+f"(acc[mt][nt][3])
                        : "r"(af[mt][0]), "r"(af[mt][1]), "r"(af[mt][2]), "r"(af[mt][3]),
                          "r"(bf[nt][0]), "r"(bf[nt][1]));
                }
        }

        if (kt + 2 < KT) load_tile(kt + 2, (kt + 2) % NSTAGE);
        cp_commit();           // commit every iter (possibly empty) -> stable wait counts
    }

    // epilogue: bias (+gelu, tf32-round for next GEMM), float2 stores
    #pragma unroll
    for (int mt = 0; mt < 4; mt++) {
        int r0 = rowBase + wm * 64 + mt * 16 + g;
        #pragma unroll
        for (int nt = 0; nt < 4; nt++) {
            int c0 = colBase + wn * 32 + nt * 8 + tg * 2;
            float b0 = __ldg(bias + c0), b1 = __ldg(bias + c0 + 1);
            float v0 = acc[mt][nt][0] + b0, v1 = acc[mt][nt][1] + b1;
            float v2 = acc[mt][nt][2] + b0, v3 = acc[mt][nt][3] + b1;
            if (PHASE1) {
                v0 = to_tf32(gelu_tanh(v0)); v1 = to_tf32(gelu_tanh(v1));
                v2 = to_tf32(gelu_tanh(v2)); v3 = to_tf32(gelu_tanh(v3));
            }
            *(float2*)&C[(size_t)r0       * N + c0] = make_float2(v0, v1);
            *(float2*)&C[(size_t)(r0 + 8) * N + c0] = make_float2(v2, v3);
        }
    }
}

// ---------------- 6. combine ----------------
__global__ void combine_kernel(float* __restrict__ out) {
    int s = blockIdx.x;
    int t = threadIdx.x;
    int slot = g_tok_slot[s];
    float4* o = (float4*)(out + (size_t)s * ODIM);
    if (slot < 0) {
        o[t] = make_float4(0.f, 0.f, 0.f, 0.f);
        return;
    }
    float gv = g_gate[s];
    float4 v = ((const float4*)(g_eout + (size_t)slot * ODIM))[t];
    v.x *= gv; v.y *= gv; v.z *= gv; v.w *= gv;
    o[t] = v;
}

// ---------------- 7. l_aux ----------------
__global__ void laux_kernel(float* __restrict__ out, int out_size) {
    __shared__ float sp[4][256];
    __shared__ float sc[4][256];
    int t = threadIdx.x;
    float p[4] = {0.f, 0.f, 0.f, 0.f};
    float c[4] = {0.f, 0.f, 0.f, 0.f};
    for (int s = t; s < S_TOK; s += 256) {
        float4 pr = ((const float4*)g_probs)[s];
        p[0] += pr.x; p[1] += pr.y; p[2] += pr.z; p[3] += pr.w;
        int e = g_eidx[s];
        #pragma unroll
        for (int k = 0; k < 4; k++) c[k] += (e == k) ? 1.f : 0.f;
    }
    #pragma unroll
    for (int k = 0; k < 4; k++) { sp[k][t] = p[k]; sc[k][t] = c[k]; }
    __syncthreads();
    for (int off = 128; off; off >>= 1) {
        if (t < off) {
            #pragma unroll
            for (int k = 0; k < 4; k++) {
                sp[k][t] += sp[k][t + off];
                sc[k][t] += sc[k][t + off];
            }
        }
        __syncthreads();
    }
    if (t == 0 && out_size > S_TOK * ODIM) {
        float inv = 1.0f / (float)S_TOK;
        float l = 0.f;
        #pragma unroll
        for (int k = 0; k < 4; k++) l += (sp[k][0] * inv) * (sc[k][0] * inv);
        out[(size_t)S_TOK * ODIM] = l * (float)EEXP;
    }
}

// ---------------- launch ----------------
extern "C" void kernel_launch(void* const* d_in, const int* in_sizes, int n_in,
                              void* d_out, int out_size) {
    (void)in_sizes; (void)n_in;
    const float* hs = (const float*)d_in[0];   // [8,1024,1024]
    const float* gw = (const float*)d_in[1];   // [1024,4]
    const float* w1 = (const float*)d_in[2];   // [4,1024,4096]
    const float* b1 = (const float*)d_in[3];   // [4,4096]
    const float* w2 = (const float*)d_in[4];   // [4,4096,1024]
    const float* b2 = (const float*)d_in[5];   // [4,1024]
    float* out = (float*)d_out;

    cudaFuncSetAttribute(moe_gemm<true>,
                         cudaFuncAttributeMaxDynamicSharedMemorySize, SMEM_BYTES);
    cudaFuncSetAttribute(moe_gemm<false>,
                         cudaFuncAttributeMaxDynamicSharedMemorySize, SMEM_BYTES);

    float* w1r; cudaGetSymbolAddress((void**)&w1r, g_w1r);
    float* w2r; cudaGetSymbolAddress((void**)&w2r, g_w2r);

    const int W1_N4 = EEXP * MDIM * HDIM / 4;
    const int W2_N4 = EEXP * HDIM * ODIM / 4;

    gate_kernel<<<S_TOK / 8, 256>>>(hs, gw);
    scan_kernel<<<1, 1024>>>();
    gather_kernel<<<EEXP * CCAP, 256>>>(hs);
    round_kernel<<<(W1_N4 + 255) / 256, 256>>>(w1, w1r, W1_N4);
    round_kernel<<<(W2_N4 + 255) / 256, 256>>>(w2, w2r, W2_N4);
    moe_gemm<true ><<<dim3(HDIM / GBN, CCAP / GBM, EEXP), 256, SMEM_BYTES>>>(w1r, b1);
    moe_gemm<false><<<dim3(ODIM / GBN, CCAP / GBM, EEXP), 256, SMEM_BYTES>>>(w2r, b2);
    combine_kernel<<<S_TOK, 256>>>(out);
    laux_kernel<<<1, 256>>>(out, out_size);
}

// round 4
// speedup vs baseline: 1.5521x; 1.1251x over previous
#include <cuda_runtime.h>
#include <cstdint>

// Problem dims (fixed by the dataset)
#define S_TOK 8192      // B*T
#define MDIM  1024
#define HDIM  4096
#define ODIM  1024
#define EEXP  4
#define CCAP  2048      // ceil(S/E)

// ---------------- device scratch (no cudaMalloc allowed) ----------------
__device__ float g_disp [(size_t)EEXP * CCAP * MDIM];   // 32 MB  dispatched tokens (tf32)
__device__ float g_h    [(size_t)EEXP * CCAP * HDIM];   // 128 MB fc1 activations (tf32)
__device__ float g_eout [(size_t)EEXP * CCAP * ODIM];   // 32 MB  fc2 outputs
__device__ float g_w1r  [(size_t)EEXP * MDIM * HDIM];   // 64 MB  w1 rounded to tf32
__device__ float g_w2r  [(size_t)EEXP * HDIM * ODIM];   // 64 MB  w2 rounded to tf32
__device__ float g_probs[S_TOK * 4];
__device__ float g_gate [S_TOK];
__device__ int   g_eidx [S_TOK];
__device__ int   g_tok_slot[S_TOK];
__device__ int   g_slot_tok[EEXP * CCAP];

// ---------------- helpers ----------------
__device__ __forceinline__ float to_tf32(float x) {
    uint32_t u;
    asm volatile("cvt.rna.tf32.f32 %0, %1;" : "=r"(u) : "f"(x));
    return __uint_as_float(u);
}

__device__ __forceinline__ float gelu_tanh(float x) {
    float x3 = x * x * x;
    return 0.5f * x * (1.0f + tanhf(0.7978845608028654f * (x + 0.044715f * x3)));
}

__device__ __forceinline__ uint32_t smem_u32(const void* p) {
    uint32_t a;
    asm("{ .reg .u64 t; cvta.to.shared.u64 t, %1; cvt.u32.u64 %0, t; }" : "=r"(a) : "l"(p));
    return a;
}

__device__ __forceinline__ void cp16(uint32_t s, const void* g) {
    asm volatile("cp.async.cg.shared.global [%0], [%1], 16;\n" :: "r"(s), "l"(g));
}
__device__ __forceinline__ void cp_commit() {
    asm volatile("cp.async.commit_group;\n" ::: "memory");
}
template<int N> __device__ __forceinline__ void cp_wait() {
    asm volatile("cp.async.wait_group %0;\n" :: "n"(N) : "memory");
}

// ---------------- 1. gate ----------------
__global__ void gate_kernel(const float* __restrict__ feats,
                            const float* __restrict__ gw) {
    int gtid = blockIdx.x * blockDim.x + threadIdx.x;
    int tok  = gtid >> 5;
    int lane = threadIdx.x & 31;
    if (tok >= S_TOK) return;

    const float* f = feats + (size_t)tok * MDIM;
    float a0 = 0.f, a1 = 0.f, a2 = 0.f, a3 = 0.f;
    for (int m = lane; m < MDIM; m += 32) {
        float fv = f[m];
        float4 w = __ldg((const float4*)gw + m);
        a0 += fv * w.x; a1 += fv * w.y; a2 += fv * w.z; a3 += fv * w.w;
    }
    #pragma unroll
    for (int o = 16; o; o >>= 1) {
        a0 += __shfl_down_sync(0xffffffffu, a0, o);
        a1 += __shfl_down_sync(0xffffffffu, a1, o);
        a2 += __shfl_down_sync(0xffffffffu, a2, o);
        a3 += __shfl_down_sync(0xffffffffu, a3, o);
    }
    if (lane == 0) {
        float l[4] = {a0, a1, a2, a3};
        float mx = l[0]; int ai = 0;
        #pragma unroll
        for (int e = 1; e < 4; e++) if (l[e] > mx) { mx = l[e]; ai = e; }
        float p[4], s = 0.f;
        #pragma unroll
        for (int e = 0; e < 4; e++) { p[e] = expf(l[e] - mx); s += p[e]; }
        float inv = 1.0f / s;
        ((float4*)g_probs)[tok] = make_float4(p[0]*inv, p[1]*inv, p[2]*inv, p[3]*inv);
        g_eidx[tok] = ai;
        g_gate[tok] = p[ai] * inv;
    }
}

// ---------------- 2. capacity scan ----------------
__global__ void scan_kernel() {
    __shared__ unsigned long long sc[1024];
    int tid = threadIdx.x;

    for (int i = tid; i < EEXP * CCAP; i += 1024) g_slot_tok[i] = -1;

    int el[8];
    unsigned long long cnt = 0ull;
    #pragma unroll
    for (int j = 0; j < 8; j++) {
        int e = g_eidx[tid * 8 + j];
        el[j] = e;
        cnt += 1ull << (e * 16);
    }
    sc[tid] = cnt;
    __syncthreads();
    for (int off = 1; off < 1024; off <<= 1) {
        unsigned long long v = 0ull;
        if (tid >= off) v = sc[tid - off];
        __syncthreads();
        sc[tid] += v;
        __syncthreads();
    }
    unsigned long long base = sc[tid] - cnt;
    #pragma unroll
    for (int j = 0; j < 8; j++) {
        int e   = el[j];
        int pos = (int)((base >> (e * 16)) & 0xFFFFull);
        int tok = tid * 8 + j;
        if (pos < CCAP) {
            int slot = e * CCAP + pos;
            g_tok_slot[tok]  = slot;
            g_slot_tok[slot] = tok;
        } else {
            g_tok_slot[tok] = -1;
        }
        base += 1ull << (e * 16);
    }
}

// ---------------- 3. gather (tf32-rounded) ----------------
__global__ void gather_kernel(const float* __restrict__ feats) {
    int slot = blockIdx.x;
    int t    = threadIdx.x;
    int tok  = g_slot_tok[slot];
    float4* d = (float4*)(g_disp + (size_t)slot * MDIM);
    if (tok < 0) {
        d[t] = make_float4(0.f, 0.f, 0.f, 0.f);
    } else {
        float4 v = ((const float4*)(feats + (size_t)tok * MDIM))[t];
        v.x = to_tf32(v.x); v.y = to_tf32(v.y);
        v.z = to_tf32(v.z); v.w = to_tf32(v.w);
        d[t] = v;
    }
}

// ---------------- 3b. round weights to tf32 (elementwise) ----------------
__global__ void round_kernel(const float* __restrict__ src, float* __restrict__ dst,
                             int n4) {
    int i = blockIdx.x * blockDim.x + threadIdx.x;
    if (i >= n4) return;
    float4 v = ((const float4*)src)[i];
    v.x = to_tf32(v.x); v.y = to_tf32(v.y);
    v.z = to_tf32(v.z); v.w = to_tf32(v.w);
    ((float4*)dst)[i] = v;
}

// ---------------- 4/5. grouped GEMM: tf32 mma.sync + 3-stage cp.async ------
// CTA tile 128x128, 4 warps, warp tile 64x64 (2x2 warp grid).
// Fragment intensity 0.125 B/MAC -> smem crossbar no longer binds.
// PHASE1: g_disp[2048,1024] @ w1[1024,4096] -> gelu -> g_h (tf32)
// else  : g_h  [2048,4096] @ w2[4096,1024] ->          g_eout
#define GBM 128
#define GBN 128
#define GBK 32
#define NSTAGE 3
#define SA_STRIDE 36                    // floats per A row: bank = 4g+tg (+kk) -> conflict-free
#define SB_STRIDE 136                   // floats per B row: bank = 8tg+g+8nt -> conflict-free
#define SA_FLOATS (GBM * SA_STRIDE)     // 4608
#define SB_FLOATS (GBK * SB_STRIDE)     // 4352
#define SMEM_FLOATS (NSTAGE * (SA_FLOATS + SB_FLOATS))
#define SMEM_BYTES  (SMEM_FLOATS * 4)   // 107520 B -> 2 CTAs/SM

template <bool PHASE1>
__global__ void __launch_bounds__(128, 2) moe_gemm(const float* __restrict__ Ball,
                                                   const float* __restrict__ biasAll) {
    constexpr int K  = PHASE1 ? MDIM : HDIM;
    constexpr int N  = PHASE1 ? HDIM : ODIM;
    constexpr int KT = K / GBK;

    extern __shared__ float smem[];
    float* As = smem;                       // [NSTAGE][GBM][SA_STRIDE]
    float* Bs = smem + NSTAGE * SA_FLOATS;  // [NSTAGE][GBK][SB_STRIDE]

    const float* Aall = PHASE1 ? g_disp : g_h;
    float*       Call = PHASE1 ? g_h    : g_eout;

    const int e = blockIdx.z;
    const float* A    = Aall    + (size_t)e * CCAP * K;
    const float* B    = Ball    + (size_t)e * K * N;
    const float* bias = biasAll + (size_t)e * N;
    float*       C    = Call    + (size_t)e * CCAP * N;

    const int tid  = threadIdx.x;
    const int warp = tid >> 5, lane = tid & 31;
    const int wm = warp >> 1, wn = warp & 1;      // 2x2 warp grid, warp tile 64x64
    const int g  = lane >> 2, tg = lane & 3;
    const int rowBase = blockIdx.y * GBM;
    const int colBase = blockIdx.x * GBN;

    const float* Ag = A + (size_t)rowBase * K;
    const float* Bg = B + colBase;

    const uint32_t sb = smem_u32(smem);

    // thread's fixed load coordinates (128 threads)
    const int a_r  = tid >> 3;            // 0..15 (+16*i, 8 iters)
    const int a_kc = (tid & 7) * 4;       // 0,4,..28
    const int b_kr = tid >> 5;            // 0..3  (+4*i, 8 iters)
    const int b_nc = (tid & 31) * 4;      // 0..124

    auto load_tile = [&](int kt, int stage) {
        const int k0 = kt * GBK;
        uint32_t sA = sb + (stage * SA_FLOATS) * 4;
        uint32_t sB = sb + (NSTAGE * SA_FLOATS + stage * SB_FLOATS) * 4;
        #pragma unroll
        for (int i = 0; i < 8; i++) {
            int r = a_r + i * 16;
            cp16(sA + (r * SA_STRIDE + a_kc) * 4, Ag + (size_t)r * K + k0 + a_kc);
        }
        #pragma unroll
        for (int i = 0; i < 8; i++) {
            int kr = b_kr + i * 4;
            cp16(sB + (kr * SB_STRIDE + b_nc) * 4, Bg + (size_t)(k0 + kr) * N + b_nc);
        }
    };

    float acc[4][8][4];
    #pragma unroll
    for (int i = 0; i < 4; i++)
        #pragma unroll
        for (int j = 0; j < 8; j++)
            #pragma unroll
            for (int r = 0; r < 4; r++) acc[i][j][r] = 0.f;

    // prologue: stages 0,1
    load_tile(0, 0); cp_commit();
    load_tile(1, 1); cp_commit();

    for (int kt = 0; kt < KT; kt++) {
        const int stage = kt % NSTAGE;
        cp_wait<1>();          // tile kt resident (only the newest group may be pending)
        __syncthreads();

        const float* Ast = As + stage * SA_FLOATS;
        const float* Bst = Bs + stage * SB_FLOATS;

        #pragma unroll
        for (int ks = 0; ks < 4; ks++) {
            const int kk = ks * 8;
            uint32_t af[4][4], bf[8][2];
            #pragma unroll
            for (int mt = 0; mt < 4; mt++) {
                const float* ar = Ast + (size_t)(wm * 64 + mt * 16 + g) * SA_STRIDE + kk + tg;
                af[mt][0] = __float_as_uint(ar[0]);
                af[mt][1] = __float_as_uint(ar[8 * SA_STRIDE]);
                af[mt][2] = __float_as_uint(ar[4]);
                af[mt][3] = __float_as_uint(ar[8 * SA_STRIDE + 4]);
            }
            #pragma unroll
            for (int nt = 0; nt < 8; nt++) {
                int n = wn * 64 + nt * 8 + g;
                bf[nt][0] = __float_as_uint(Bst[(kk + tg) * SB_STRIDE + n]);
                bf[nt][1] = __float_as_uint(Bst[(kk + tg + 4) * SB_STRIDE + n]);
            }
            #pragma unroll
            for (int mt = 0; mt < 4; mt++)
                #pragma unroll
                for (int nt = 0; nt < 8; nt++) {
                    asm volatile(
                        "mma.sync.aligned.m16n8k8.row.col.f32.tf32.tf32.f32 "
                        "{%0,%1,%2,%3}, {%4,%5,%6,%7}, {%8,%9}, {%0,%1,%2,%3};\n"
                        : "+f"(acc[mt][nt][0]), "+f"(acc[mt][nt][1]),
                          "+f"(acc[mt][nt][2]), "+f"(acc[mt][nt][3])
                        : "r"(af[mt][0]), "r"(af[mt][1]), "r"(af[mt][2]), "r"(af[mt][3]),
                          "r"(bf[nt][0]), "r"(bf[nt][1]));
                }
        }

        if (kt + 2 < KT) load_tile(kt + 2, (kt + 2) % NSTAGE);
        cp_commit();           // commit every iter (possibly empty) -> stable wait counts
    }

    // epilogue: bias (+gelu, tf32-round for next GEMM), float2 stores
    #pragma unroll
    for (int mt = 0; mt < 4; mt++) {
        int r0 = rowBase + wm * 64 + mt * 16 + g;
        #pragma unroll
        for (int nt = 0; nt < 8; nt++) {
            int c0 = colBase + wn * 64 + nt * 8 + tg * 2;
            float b0 = __ldg(bias + c0), b1 = __ldg(bias + c0 + 1);
            float v0 = acc[mt][nt][0] + b0, v1 = acc[mt][nt][1] + b1;
            float v2 = acc[mt][nt][2] + b0, v3 = acc[mt][nt][3] + b1;
            if (PHASE1) {
                v0 = to_tf32(gelu_tanh(v0)); v1 = to_tf32(gelu_tanh(v1));
                v2 = to_tf32(gelu_tanh(v2)); v3 = to_tf32(gelu_tanh(v3));
            }
            *(float2*)&C[(size_t)r0       * N + c0] = make_float2(v0, v1);
            *(float2*)&C[(size_t)(r0 + 8) * N + c0] = make_float2(v2, v3);
        }
    }
}

// ---------------- 6. combine ----------------
__global__ void combine_kernel(float* __restrict__ out) {
    int s = blockIdx.x;
    int t = threadIdx.x;
    int slot = g_tok_slot[s];
    float4* o = (float4*)(out + (size_t)s * ODIM);
    if (slot < 0) {
        o[t] = make_float4(0.f, 0.f, 0.f, 0.f);
        return;
    }
    float gv = g_gate[s];
    float4 v = ((const float4*)(g_eout + (size_t)slot * ODIM))[t];
    v.x *= gv; v.y *= gv; v.z *= gv; v.w *= gv;
    o[t] = v;
}

// ---------------- 7. l_aux ----------------
__global__ void laux_kernel(float* __restrict__ out, int out_size) {
    __shared__ float sp[4][256];
    __shared__ float sc[4][256];
    int t = threadIdx.x;
    float p[4] = {0.f, 0.f, 0.f, 0.f};
    float c[4] = {0.f, 0.f, 0.f, 0.f};
    for (int s = t; s < S_TOK; s += 256) {
        float4 pr = ((const float4*)g_probs)[s];
        p[0] += pr.x; p[1] += pr.y; p[2] += pr.z; p[3] += pr.w;
        int e = g_eidx[s];
        #pragma unroll
        for (int k = 0; k < 4; k++) c[k] += (e == k) ? 1.f : 0.f;
    }
    #pragma unroll
    for (int k = 0; k < 4; k++) { sp[k][t] = p[k]; sc[k][t] = c[k]; }
    __syncthreads();
    for (int off = 128; off; off >>= 1) {
        if (t < off) {
            #pragma unroll
            for (int k = 0; k < 4; k++) {
                sp[k][t] += sp[k][t + off];
                sc[k][t] += sc[k][t + off];
            }
        }
        __syncthreads();
    }
    if (t == 0 && out_size > S_TOK * ODIM) {
        float inv = 1.0f / (float)S_TOK;
        float l = 0.f;
        #pragma unroll
        for (int k = 0; k < 4; k++) l += (sp[k][0] * inv) * (sc[k][0] * inv);
        out[(size_t)S_TOK * ODIM] = l * (float)EEXP;
    }
}

// ---------------- launch ----------------
extern "C" void kernel_launch(void* const* d_in, const int* in_sizes, int n_in,
                              void* d_out, int out_size) {
    (void)in_sizes; (void)n_in;
    const float* hs = (const float*)d_in[0];   // [8,1024,1024]
    const float* gw = (const float*)d_in[1];   // [1024,4]
    const float* w1 = (const float*)d_in[2];   // [4,1024,4096]
    const float* b1 = (const float*)d_in[3];   // [4,4096]
    const float* w2 = (const float*)d_in[4];   // [4,4096,1024]
    const float* b2 = (const float*)d_in[5];   // [4,1024]
    float* out = (float*)d_out;

    cudaFuncSetAttribute(moe_gemm<true>,
                         cudaFuncAttributeMaxDynamicSharedMemorySize, SMEM_BYTES);
    cudaFuncSetAttribute(moe_gemm<false>,
                         cudaFuncAttributeMaxDynamicSharedMemorySize, SMEM_BYTES);

    float* w1r; cudaGetSymbolAddress((void**)&w1r, g_w1r);
    float* w2r; cudaGetSymbolAddress((void**)&w2r, g_w2r);

    const int W1_N4 = EEXP * MDIM * HDIM / 4;
    const int W2_N4 = EEXP * HDIM * ODIM / 4;

    gate_kernel<<<S_TOK / 8, 256>>>(hs, gw);
    scan_kernel<<<1, 1024>>>();
    gather_kernel<<<EEXP * CCAP, 256>>>(hs);
    round_kernel<<<(W1_N4 + 255) / 256, 256>>>(w1, w1r, W1_N4);
    round_kernel<<<(W2_N4 + 255) / 256, 256>>>(w2, w2r, W2_N4);
    moe_gemm<true ><<<dim3(HDIM / GBN, CCAP / GBM, EEXP), 128, SMEM_BYTES>>>(w1r, b1);
    moe_gemm<false><<<dim3(ODIM / GBN, CCAP / GBM, EEXP), 128, SMEM_BYTES>>>(w2r, b2);
    combine_kernel<<<S_TOK, 256>>>(out);
    laux_kernel<<<1, 256>>>(out, out_size);
}

// round 5
// speedup vs baseline: 2.3347x; 1.5042x over previous
#include <cuda_runtime.h>
#include <cuda_fp16.h>
#include <cstdint>

// Problem dims (fixed by the dataset)
#define S_TOK 8192      // B*T
#define MDIM  1024
#define HDIM  4096
#define ODIM  1024
#define EEXP  4
#define CCAP  2048      // ceil(S/E)

// ---------------- device scratch (no cudaMalloc allowed) ----------------
__device__ __half g_disp [(size_t)EEXP * CCAP * MDIM];   // 16 MB  dispatched tokens (fp16)
__device__ __half g_h    [(size_t)EEXP * CCAP * HDIM];   // 64 MB  fc1 activations (fp16)
__device__ float  g_eout [(size_t)EEXP * CCAP * ODIM];   // 32 MB  fc2 outputs
__device__ __half g_w1t  [(size_t)EEXP * HDIM * MDIM];   // 32 MB  w1^T [E][H][M] fp16
__device__ __half g_w2t  [(size_t)EEXP * ODIM * HDIM];   // 32 MB  w2^T [E][O][H] fp16
__device__ float  g_probs[S_TOK * 4];
__device__ float  g_gate [S_TOK];
__device__ int    g_eidx [S_TOK];
__device__ int    g_tok_slot[S_TOK];
__device__ int    g_slot_tok[EEXP * CCAP];

// ---------------- helpers ----------------
__device__ __forceinline__ float gelu_tanh(float x) {
    float x3 = x * x * x;
    return 0.5f * x * (1.0f + tanhf(0.7978845608028654f * (x + 0.044715f * x3)));
}

__device__ __forceinline__ uint32_t smem_u32(const void* p) {
    uint32_t a;
    asm("{ .reg .u64 t; cvta.to.shared.u64 t, %1; cvt.u32.u64 %0, t; }" : "=r"(a) : "l"(p));
    return a;
}

__device__ __forceinline__ void cp16(uint32_t s, const void* g) {
    asm volatile("cp.async.cg.shared.global [%0], [%1], 16;\n" :: "r"(s), "l"(g));
}
__device__ __forceinline__ void cp_commit() {
    asm volatile("cp.async.commit_group;\n" ::: "memory");
}
template<int N> __device__ __forceinline__ void cp_wait() {
    asm volatile("cp.async.wait_group %0;\n" :: "n"(N) : "memory");
}

// ---------------- 1. gate ----------------
__global__ void gate_kernel(const float* __restrict__ feats,
                            const float* __restrict__ gw) {
    int gtid = blockIdx.x * blockDim.x + threadIdx.x;
    int tok  = gtid >> 5;
    int lane = threadIdx.x & 31;
    if (tok >= S_TOK) return;

    const float* f = feats + (size_t)tok * MDIM;
    float a0 = 0.f, a1 = 0.f, a2 = 0.f, a3 = 0.f;
    for (int m = lane; m < MDIM; m += 32) {
        float fv = f[m];
        float4 w = __ldg((const float4*)gw + m);
        a0 += fv * w.x; a1 += fv * w.y; a2 += fv * w.z; a3 += fv * w.w;
    }
    #pragma unroll
    for (int o = 16; o; o >>= 1) {
        a0 += __shfl_down_sync(0xffffffffu, a0, o);
        a1 += __shfl_down_sync(0xffffffffu, a1, o);
        a2 += __shfl_down_sync(0xffffffffu, a2, o);
        a3 += __shfl_down_sync(0xffffffffu, a3, o);
    }
    if (lane == 0) {
        float l[4] = {a0, a1, a2, a3};
        float mx = l[0]; int ai = 0;
        #pragma unroll
        for (int e = 1; e < 4; e++) if (l[e] > mx) { mx = l[e]; ai = e; }
        float p[4], s = 0.f;
        #pragma unroll
        for (int e = 0; e < 4; e++) { p[e] = expf(l[e] - mx); s += p[e]; }
        float inv = 1.0f / s;
        ((float4*)g_probs)[tok] = make_float4(p[0]*inv, p[1]*inv, p[2]*inv, p[3]*inv);
        g_eidx[tok] = ai;
        g_gate[tok] = p[ai] * inv;
    }
}

// ---------------- 2. capacity scan ----------------
__global__ void scan_kernel() {
    __shared__ unsigned long long sc[1024];
    int tid = threadIdx.x;

    for (int i = tid; i < EEXP * CCAP; i += 1024) g_slot_tok[i] = -1;

    int el[8];
    unsigned long long cnt = 0ull;
    #pragma unroll
    for (int j = 0; j < 8; j++) {
        int e = g_eidx[tid * 8 + j];
        el[j] = e;
        cnt += 1ull << (e * 16);
    }
    sc[tid] = cnt;
    __syncthreads();
    for (int off = 1; off < 1024; off <<= 1) {
        unsigned long long v = 0ull;
        if (tid >= off) v = sc[tid - off];
        __syncthreads();
        sc[tid] += v;
        __syncthreads();
    }
    unsigned long long base = sc[tid] - cnt;
    #pragma unroll
    for (int j = 0; j < 8; j++) {
        int e   = el[j];
        int pos = (int)((base >> (e * 16)) & 0xFFFFull);
        int tok = tid * 8 + j;
        if (pos < CCAP) {
            int slot = e * CCAP + pos;
            g_tok_slot[tok]  = slot;
            g_slot_tok[slot] = tok;
        } else {
            g_tok_slot[tok] = -1;
        }
        base += 1ull << (e * 16);
    }
}

// ---------------- 3. gather (fp16) ----------------
__global__ void gather_kernel(const float* __restrict__ feats) {
    int slot = blockIdx.x;
    int t    = threadIdx.x;                 // 256 threads, 4 halves each (M=1024)
    int tok  = g_slot_tok[slot];
    uint2* d = (uint2*)(g_disp + (size_t)slot * MDIM) + t;
    if (tok < 0) {
        *d = make_uint2(0u, 0u);
    } else {
        float4 v = ((const float4*)(feats + (size_t)tok * MDIM))[t];
        __half2 h0 = __floats2half2_rn(v.x, v.y);
        __half2 h1 = __floats2half2_rn(v.z, v.w);
        *d = make_uint2(*(uint32_t*)&h0, *(uint32_t*)&h1);
    }
}

// ---------------- 3b. weight transpose+convert [E][K][N]f32 -> [E][N][K]f16 -
__global__ void transpose_kernel(const float* __restrict__ w, __half* __restrict__ wt,
                                 int K, int N) {
    __shared__ float t[32][33];
    int e  = blockIdx.z;
    int k0 = blockIdx.y * 32, n0 = blockIdx.x * 32;
    const float* we = w  + (size_t)e * K * N;
    __half*     wte = wt + (size_t)e * K * N;
    int tx = threadIdx.x, ty = threadIdx.y;   // 32x8
    #pragma unroll
    for (int i = 0; i < 32; i += 8)
        t[ty + i][tx] = we[(size_t)(k0 + ty + i) * N + n0 + tx];
    __syncthreads();
    #pragma unroll
    for (int i = 0; i < 32; i += 8)
        wte[(size_t)(n0 + ty + i) * K + k0 + tx] = __float2half_rn(t[tx][ty + i]);
}

// ---------------- 4/5. grouped GEMM: fp16 mma.sync m16n8k16 ----------------
// CTA tile 128x128, 4 warps, warp tile 64x64 (2x2). 4-stage cp.async.
// Both A and B smem tiles are [row][k] half, k-contiguous, stride 40 halves:
// fragment loads are aligned LDS.U32 with bank = (20g + tg) mod 32 -> 32-perm.
// PHASE1: g_disp[2048,1024]h @ w1t -> gelu -> g_h (h)
// else  : g_h  [2048,4096]h @ w2t ->          g_eout (f32)
#define GBM 128
#define GBN 128
#define GBK 32
#define NSTAGE 4
#define SAH 40                           // halves per A row (32 + pad 8) = 80 B
#define SBH 40                           // halves per B row
#define SA_HALF (GBM * SAH)              // 5120 halves = 10240 B
#define SB_HALF (GBN * SBH)              // 5120 halves = 10240 B
#define SMEM_BYTES (NSTAGE * (SA_HALF + SB_HALF) * 2)   // 81920 B -> 2 CTAs/SM

template <bool PHASE1>
__global__ void __launch_bounds__(128, 2) moe_gemm(const __half* __restrict__ Ball,
                                                   const float* __restrict__ biasAll) {
    constexpr int K  = PHASE1 ? MDIM : HDIM;
    constexpr int N  = PHASE1 ? HDIM : ODIM;
    constexpr int KT = K / GBK;

    extern __shared__ __half smem[];
    __half* As = smem;                        // [NSTAGE][GBM][SAH]
    __half* Bs = smem + NSTAGE * SA_HALF;     // [NSTAGE][GBN][SBH]

    const __half* Aall = PHASE1 ? g_disp : g_h;

    const int e = blockIdx.z;
    const __half* A    = Aall    + (size_t)e * CCAP * K;
    const __half* B    = Ball    + (size_t)e * (size_t)N * K;   // [N][K] half
    const float*  bias = biasAll + (size_t)e * N;

    const int tid  = threadIdx.x;
    const int warp = tid >> 5, lane = tid & 31;
    const int wm = warp >> 1, wn = warp & 1;      // 2x2 warp grid, warp tile 64x64
    const int g  = lane >> 2, tg = lane & 3;
    const int rowBase = blockIdx.y * GBM;
    const int colBase = blockIdx.x * GBN;

    const __half* Ag = A + (size_t)rowBase * K;
    const __half* Bg = B + (size_t)colBase * K;

    const uint32_t sb = smem_u32(smem);

    // cp.async coords: 128 rows x 4 chunks(8 halves) for each of A and B
    const int l_r  = tid >> 2;            // 0..31 (+32*i, 4 iters)
    const int l_kc = (tid & 3) * 8;       // 0,8,16,24 halves

    auto load_tile = [&](int kt, int stage) {
        const int k0 = kt * GBK;
        uint32_t sA = sb + (stage * SA_HALF) * 2;
        uint32_t sB = sb + (NSTAGE * SA_HALF + stage * SB_HALF) * 2;
        #pragma unroll
        for (int i = 0; i < 4; i++) {
            int r = l_r + i * 32;
            cp16(sA + (r * SAH + l_kc) * 2, Ag + (size_t)r * K + k0 + l_kc);
        }
        #pragma unroll
        for (int i = 0; i < 4; i++) {
            int r = l_r + i * 32;
            cp16(sB + (r * SBH + l_kc) * 2, Bg + (size_t)r * K + k0 + l_kc);
        }
    };

    float acc[4][8][4];
    #pragma unroll
    for (int i = 0; i < 4; i++)
        #pragma unroll
        for (int j = 0; j < 8; j++)
            #pragma unroll
            for (int r = 0; r < 4; r++) acc[i][j][r] = 0.f;

    // prologue: stages 0..2
    load_tile(0, 0); cp_commit();
    load_tile(1, 1); cp_commit();
    load_tile(2, 2); cp_commit();

    for (int kt = 0; kt < KT; kt++) {
        const int stage = kt & (NSTAGE - 1);
        cp_wait<2>();          // tile kt resident (2 newest groups may be pending)
        __syncthreads();

        const __half* Ast = As + stage * SA_HALF;
        const __half* Bst = Bs + stage * SB_HALF;

        #pragma unroll
        for (int ks = 0; ks < 2; ks++) {      // two k16 steps per 32-k tile
            const int kk = ks * 16;
            uint32_t af[4][4], bf[8][2];
            #pragma unroll
            for (int mt = 0; mt < 4; mt++) {
                const __half* ar = Ast + (size_t)(wm * 64 + mt * 16 + g) * SAH + kk + 2 * tg;
                af[mt][0] = *(const uint32_t*)(ar);
                af[mt][1] = *(const uint32_t*)(ar + 8 * SAH);
                af[mt][2] = *(const uint32_t*)(ar + 8);
                af[mt][3] = *(const uint32_t*)(ar + 8 * SAH + 8);
            }
            #pragma unroll
            for (int nt = 0; nt < 8; nt++) {
                const __half* br = Bst + (size_t)(wn * 64 + nt * 8 + g) * SBH + kk + 2 * tg;
                bf[nt][0] = *(const uint32_t*)(br);
                bf[nt][1] = *(const uint32_t*)(br + 8);
            }
            #pragma unroll
            for (int mt = 0; mt < 4; mt++)
                #pragma unroll
                for (int nt = 0; nt < 8; nt++) {
                    asm volatile(
                        "mma.sync.aligned.m16n8k16.row.col.f32.f16.f16.f32 "
                        "{%0,%1,%2,%3}, {%4,%5,%6,%7}, {%8,%9}, {%0,%1,%2,%3};\n"
                        : "+f"(acc[mt][nt][0]), "+f"(acc[mt][nt][1]),
                          "+f"(acc[mt][nt][2]), "+f"(acc[mt][nt][3])
                        : "r"(af[mt][0]), "r"(af[mt][1]), "r"(af[mt][2]), "r"(af[mt][3]),
                          "r"(bf[nt][0]), "r"(bf[nt][1]));
                }
        }

        if (kt + 3 < KT) load_tile(kt + 3, (kt + 3) & (NSTAGE - 1));
        cp_commit();           // commit every iter (possibly empty) -> stable wait counts
    }

    // epilogue: bias (+gelu); PHASE1 stores half2 into g_h, PHASE2 float2 into g_eout
    #pragma unroll
    for (int mt = 0; mt < 4; mt++) {
        int r0 = rowBase + wm * 64 + mt * 16 + g;
        #pragma unroll
        for (int nt = 0; nt < 8; nt++) {
            int c0 = colBase + wn * 64 + nt * 8 + tg * 2;
            float b0 = __ldg(bias + c0), b1 = __ldg(bias + c0 + 1);
            float v0 = acc[mt][nt][0] + b0, v1 = acc[mt][nt][1] + b1;
            float v2 = acc[mt][nt][2] + b0, v3 = acc[mt][nt][3] + b1;
            if (PHASE1) {
                __half2 h01 = __floats2half2_rn(gelu_tanh(v0), gelu_tanh(v1));
                __half2 h23 = __floats2half2_rn(gelu_tanh(v2), gelu_tanh(v3));
                __half* Ch = g_h + (size_t)e * CCAP * N;
                *(__half2*)&Ch[(size_t)r0       * N + c0] = h01;
                *(__half2*)&Ch[(size_t)(r0 + 8) * N + c0] = h23;
            } else {
                float* Cf = g_eout + (size_t)e * CCAP * N;
                *(float2*)&Cf[(size_t)r0       * N + c0] = make_float2(v0, v1);
                *(float2*)&Cf[(size_t)(r0 + 8) * N + c0] = make_float2(v2, v3);
            }
        }
    }
}

// ---------------- 6. combine ----------------
__global__ void combine_kernel(float* __restrict__ out) {
    int s = blockIdx.x;
    int t = threadIdx.x;
    int slot = g_tok_slot[s];
    float4* o = (float4*)(out + (size_t)s * ODIM);
    if (slot < 0) {
        o[t] = make_float4(0.f, 0.f, 0.f, 0.f);
        return;
    }
    float gv = g_gate[s];
    float4 v = ((const float4*)(g_eout + (size_t)slot * ODIM))[t];
    v.x *= gv; v.y *= gv; v.z *= gv; v.w *= gv;
    o[t] = v;
}

// ---------------- 7. l_aux ----------------
__global__ void laux_kernel(float* __restrict__ out, int out_size) {
    __shared__ float sp[4][256];
    __shared__ float sc[4][256];
    int t = threadIdx.x;
    float p[4] = {0.f, 0.f, 0.f, 0.f};
    float c[4] = {0.f, 0.f, 0.f, 0.f};
    for (int s = t; s < S_TOK; s += 256) {
        float4 pr = ((const float4*)g_probs)[s];
        p[0] += pr.x; p[1] += pr.y; p[2] += pr.z; p[3] += pr.w;
        int e = g_eidx[s];
        #pragma unroll
        for (int k = 0; k < 4; k++) c[k] += (e == k) ? 1.f : 0.f;
    }
    #pragma unroll
    for (int k = 0; k < 4; k++) { sp[k][t] = p[k]; sc[k][t] = c[k]; }
    __syncthreads();
    for (int off = 128; off; off >>= 1) {
        if (t < off) {
            #pragma unroll
            for (int k = 0; k < 4; k++) {
                sp[k][t] += sp[k][t + off];
                sc[k][t] += sc[k][t + off];
            }
        }
        __syncthreads();
    }
    if (t == 0 && out_size > S_TOK * ODIM) {
        float inv = 1.0f / (float)S_TOK;
        float l = 0.f;
        #pragma unroll
        for (int k = 0; k < 4; k++) l += (sp[k][0] * inv) * (sc[k][0] * inv);
        out[(size_t)S_TOK * ODIM] = l * (float)EEXP;
    }
}

// ---------------- launch ----------------
extern "C" void kernel_launch(void* const* d_in, const int* in_sizes, int n_in,
                              void* d_out, int out_size) {
    (void)in_sizes; (void)n_in;
    const float* hs = (const float*)d_in[0];   // [8,1024,1024]
    const float* gw = (const float*)d_in[1];   // [1024,4]
    const float* w1 = (const float*)d_in[2];   // [4,1024,4096]
    const float* b1 = (const float*)d_in[3];   // [4,4096]
    const float* w2 = (const float*)d_in[4];   // [4,4096,1024]
    const float* b2 = (const float*)d_in[5];   // [4,1024]
    float* out = (float*)d_out;

    cudaFuncSetAttribute(moe_gemm<true>,
                         cudaFuncAttributeMaxDynamicSharedMemorySize, SMEM_BYTES);
    cudaFuncSetAttribute(moe_gemm<false>,
                         cudaFuncAttributeMaxDynamicSharedMemorySize, SMEM_BYTES);

    __half* w1t; cudaGetSymbolAddress((void**)&w1t, g_w1t);
    __half* w2t; cudaGetSymbolAddress((void**)&w2t, g_w2t);

    gate_kernel<<<S_TOK / 8, 256>>>(hs, gw);
    scan_kernel<<<1, 1024>>>();
    gather_kernel<<<EEXP * CCAP, 256>>>(hs);
    transpose_kernel<<<dim3(HDIM / 32, MDIM / 32, EEXP), dim3(32, 8)>>>(w1, w1t, MDIM, HDIM);
    transpose_kernel<<<dim3(ODIM / 32, HDIM / 32, EEXP), dim3(32, 8)>>>(w2, w2t, HDIM, ODIM);
    moe_gemm<true ><<<dim3(HDIM / GBN, CCAP / GBM, EEXP), 128, SMEM_BYTES>>>(w1t, b1);
    moe_gemm<false><<<dim3(ODIM / GBN, CCAP / GBM, EEXP), 128, SMEM_BYTES>>>(w2t, b2);
    combine_kernel<<<S_TOK, 256>>>(out);
    laux_kernel<<<1, 256>>>(out, out_size);
}

// round 6
// speedup vs baseline: 2.9636x; 1.2694x over previous
#include <cuda_runtime.h>
#include <cuda_fp16.h>
#include <cstdint>

// Problem dims (fixed by the dataset)
#define S_TOK 8192      // B*T
#define MDIM  1024
#define HDIM  4096
#define ODIM  1024
#define EEXP  4
#define CCAP  2048      // ceil(S/E)

// ---------------- device scratch (no cudaMalloc allowed) ----------------
__device__ __half g_disp [(size_t)EEXP * CCAP * MDIM];   // 16 MB  dispatched tokens (fp16)
__device__ __half g_h    [(size_t)EEXP * CCAP * HDIM];   // 64 MB  fc1 activations (fp16)
__device__ __half g_w1t  [(size_t)EEXP * HDIM * MDIM];   // 32 MB  w1^T [E][H][M] fp16
__device__ __half g_w2t  [(size_t)EEXP * ODIM * HDIM];   // 32 MB  w2^T [E][O][H] fp16
__device__ float  g_probs[S_TOK * 4];
__device__ float  g_gate [S_TOK];
__device__ int    g_eidx [S_TOK];
__device__ int    g_tok_slot[S_TOK];
__device__ int    g_slot_tok[EEXP * CCAP];

// ---------------- helpers ----------------
__device__ __forceinline__ float gelu_tanh(float x) {
    float x3 = x * x * x;
    return 0.5f * x * (1.0f + tanhf(0.7978845608028654f * (x + 0.044715f * x3)));
}

__device__ __forceinline__ uint32_t smem_u32(const void* p) {
    uint32_t a;
    asm("{ .reg .u64 t; cvta.to.shared.u64 t, %1; cvt.u32.u64 %0, t; }" : "=r"(a) : "l"(p));
    return a;
}

__device__ __forceinline__ void cp16(uint32_t s, const void* g) {
    asm volatile("cp.async.cg.shared.global [%0], [%1], 16;\n" :: "r"(s), "l"(g));
}
__device__ __forceinline__ void cp_commit() {
    asm volatile("cp.async.commit_group;\n" ::: "memory");
}
template<int N> __device__ __forceinline__ void cp_wait() {
    asm volatile("cp.async.wait_group %0;\n" :: "n"(N) : "memory");
}

__device__ __forceinline__ void ldsm_x4(uint32_t& r0, uint32_t& r1, uint32_t& r2,
                                        uint32_t& r3, uint32_t addr) {
    asm volatile("ldmatrix.sync.aligned.m8n8.x4.shared.b16 {%0,%1,%2,%3}, [%4];"
                 : "=r"(r0), "=r"(r1), "=r"(r2), "=r"(r3) : "r"(addr));
}

// ---------------- 1. gate ----------------
__global__ void gate_kernel(const float* __restrict__ feats,
                            const float* __restrict__ gw) {
    int gtid = blockIdx.x * blockDim.x + threadIdx.x;
    int tok  = gtid >> 5;
    int lane = threadIdx.x & 31;
    if (tok >= S_TOK) return;

    const float* f = feats + (size_t)tok * MDIM;
    float a0 = 0.f, a1 = 0.f, a2 = 0.f, a3 = 0.f;
    for (int m = lane; m < MDIM; m += 32) {
        float fv = f[m];
        float4 w = __ldg((const float4*)gw + m);
        a0 += fv * w.x; a1 += fv * w.y; a2 += fv * w.z; a3 += fv * w.w;
    }
    #pragma unroll
    for (int o = 16; o; o >>= 1) {
        a0 += __shfl_down_sync(0xffffffffu, a0, o);
        a1 += __shfl_down_sync(0xffffffffu, a1, o);
        a2 += __shfl_down_sync(0xffffffffu, a2, o);
        a3 += __shfl_down_sync(0xffffffffu, a3, o);
    }
    if (lane == 0) {
        float l[4] = {a0, a1, a2, a3};
        float mx = l[0]; int ai = 0;
        #pragma unroll
        for (int e = 1; e < 4; e++) if (l[e] > mx) { mx = l[e]; ai = e; }
        float p[4], s = 0.f;
        #pragma unroll
        for (int e = 0; e < 4; e++) { p[e] = expf(l[e] - mx); s += p[e]; }
        float inv = 1.0f / s;
        ((float4*)g_probs)[tok] = make_float4(p[0]*inv, p[1]*inv, p[2]*inv, p[3]*inv);
        g_eidx[tok] = ai;
        g_gate[tok] = p[ai] * inv;
    }
}

// ---------------- 2. capacity scan ----------------
__global__ void scan_kernel() {
    __shared__ unsigned long long sc[1024];
    int tid = threadIdx.x;

    for (int i = tid; i < EEXP * CCAP; i += 1024) g_slot_tok[i] = -1;

    int el[8];
    unsigned long long cnt = 0ull;
    #pragma unroll
    for (int j = 0; j < 8; j++) {
        int e = g_eidx[tid * 8 + j];
        el[j] = e;
        cnt += 1ull << (e * 16);
    }
    sc[tid] = cnt;
    __syncthreads();
    for (int off = 1; off < 1024; off <<= 1) {
        unsigned long long v = 0ull;
        if (tid >= off) v = sc[tid - off];
        __syncthreads();
        sc[tid] += v;
        __syncthreads();
    }
    unsigned long long base = sc[tid] - cnt;
    #pragma unroll
    for (int j = 0; j < 8; j++) {
        int e   = el[j];
        int pos = (int)((base >> (e * 16)) & 0xFFFFull);
        int tok = tid * 8 + j;
        if (pos < CCAP) {
            int slot = e * CCAP + pos;
            g_tok_slot[tok]  = slot;
            g_slot_tok[slot] = tok;
        } else {
            g_tok_slot[tok] = -1;
        }
        base += 1ull << (e * 16);
    }
}

// ---------------- 3. gather (fp16) ----------------
__global__ void gather_kernel(const float* __restrict__ feats) {
    int slot = blockIdx.x;
    int t    = threadIdx.x;                 // 256 threads, 4 halves each (M=1024)
    int tok  = g_slot_tok[slot];
    uint2* d = (uint2*)(g_disp + (size_t)slot * MDIM) + t;
    if (tok < 0) {
        *d = make_uint2(0u, 0u);
    } else {
        float4 v = ((const float4*)(feats + (size_t)tok * MDIM))[t];
        __half2 h0 = __floats2half2_rn(v.x, v.y);
        __half2 h1 = __floats2half2_rn(v.z, v.w);
        *d = make_uint2(*(uint32_t*)&h0, *(uint32_t*)&h1);
    }
}

// ---------------- 3b. zero output rows of dropped tokens -------------------
__global__ void zero_dropped(float* __restrict__ out) {
    int tok  = blockIdx.x * 8 + (threadIdx.x >> 5);
    int lane = threadIdx.x & 31;
    if (g_tok_slot[tok] >= 0) return;
    float4* o = (float4*)(out + (size_t)tok * ODIM);
    #pragma unroll
    for (int i = 0; i < 8; i++)
        o[lane + i * 32] = make_float4(0.f, 0.f, 0.f, 0.f);
}

// ---------------- 3c. weight transpose+convert [E][K][N]f32 -> [E][N][K]f16
// 64x64 tiles: float4 coalesced loads, half2 stores (128B store segments)
__global__ void transpose_kernel(const float* __restrict__ w, __half* __restrict__ wt,
                                 int K, int N) {
    __shared__ float ts[64][65];
    int e  = blockIdx.z;
    int k0 = blockIdx.y * 64, n0 = blockIdx.x * 64;
    const float* we = w  + (size_t)e * K * N;
    __half*     wte = wt + (size_t)e * K * N;
    int tid = threadIdx.x;   // 256

    #pragma unroll
    for (int i = 0; i < 4; i++) {
        int idx = tid + i * 256;
        int r = idx >> 4, c4 = (idx & 15) * 4;
        float4 v = *(const float4*)(we + (size_t)(k0 + r) * N + n0 + c4);
        ts[r][c4 + 0] = v.x; ts[r][c4 + 1] = v.y;
        ts[r][c4 + 2] = v.z; ts[r][c4 + 3] = v.w;
    }
    __syncthreads();
    #pragma unroll
    for (int i = 0; i < 8; i++) {
        int idx = tid + i * 256;
        int n = idx >> 5, kp = idx & 31;
        __half2 h = __floats2half2_rn(ts[2 * kp][n], ts[2 * kp + 1][n]);
        *(__half2*)(wte + (size_t)(n0 + n) * K + k0 + 2 * kp) = h;
    }
}

// ---------------- 4/5. grouped GEMM: fp16 mma + ldmatrix fragments ---------
// CTA tile 128x128, 4 warps, warp tile 64x64 (2x2). 4-stage cp.async.
// A [m][k], B [n][k] half tiles, stride 40 halves (80B): 80*{0..7} mod 128
// is a 16B-bank permutation -> LDSM conflict-free.
// PHASE1: g_disp[2048,1024]h @ w1t -> gelu -> g_h (h)
// else  : g_h  [2048,4096]h @ w2t -> gate-scatter -> out (f32) [fused combine]
#define GBM 128
#define GBN 128
#define GBK 32
#define NSTAGE 4
#define SAH 40                           // halves per A row (32 + pad 8) = 80 B
#define SBH 40                           // halves per B row
#define SA_HALF (GBM * SAH)              // 5120 halves = 10240 B
#define SB_HALF (GBN * SBH)              // 5120 halves = 10240 B
#define SMEM_BYTES (NSTAGE * (SA_HALF + SB_HALF) * 2)   // 81920 B -> 2 CTAs/SM

template <bool PHASE1>
__global__ void __launch_bounds__(128, 2) moe_gemm(const __half* __restrict__ Ball,
                                                   const float* __restrict__ biasAll,
                                                   float* __restrict__ outp) {
    constexpr int K  = PHASE1 ? MDIM : HDIM;
    constexpr int N  = PHASE1 ? HDIM : ODIM;
    constexpr int KT = K / GBK;

    extern __shared__ __half smem[];

    const __half* Aall = PHASE1 ? g_disp : g_h;

    const int e = blockIdx.z;
    const __half* A    = Aall    + (size_t)e * CCAP * K;
    const __half* B    = Ball    + (size_t)e * (size_t)N * K;   // [N][K] half
    const float*  bias = biasAll + (size_t)e * N;

    const int tid  = threadIdx.x;
    const int warp = tid >> 5, lane = tid & 31;
    const int wm = warp >> 1, wn = warp & 1;      // 2x2 warp grid, warp tile 64x64
    const int g  = lane >> 2, tg = lane & 3;
    const int rowBase = blockIdx.y * GBM;
    const int colBase = blockIdx.x * GBN;

    const __half* Ag = A + (size_t)rowBase * K;
    const __half* Bg = B + (size_t)colBase * K;

    const uint32_t sb = smem_u32(smem);

    // cp.async coords: 128 rows x 4 chunks(8 halves) for each of A and B
    const int l_r  = tid >> 2;            // 0..31 (+32*i, 4 iters)
    const int l_kc = (tid & 3) * 8;       // 0,8,16,24 halves

    auto load_tile = [&](int kt, int stage) {
        const int k0 = kt * GBK;
        uint32_t sA = sb + (stage * SA_HALF) * 2;
        uint32_t sB = sb + (NSTAGE * SA_HALF + stage * SB_HALF) * 2;
        #pragma unroll
        for (int i = 0; i < 4; i++) {
            int r = l_r + i * 32;
            cp16(sA + (r * SAH + l_kc) * 2, Ag + (size_t)r * K + k0 + l_kc);
        }
        #pragma unroll
        for (int i = 0; i < 4; i++) {
            int r = l_r + i * 32;
            cp16(sB + (r * SBH + l_kc) * 2, Bg + (size_t)r * K + k0 + l_kc);
        }
    };

    // per-lane ldmatrix address offsets (bytes), invariant across stages/kt
    // A x4 tile mt: matrices [m0-7,k0-7],[m8-15,k0-7],[m0-7,k8-15],[m8-15,k8-15]
    uint32_t offA[4], offB[4];
    #pragma unroll
    for (int mt = 0; mt < 4; mt++)
        offA[mt] = ((wm * 64 + mt * 16 + (lane & 15)) * SAH + ((lane >> 4) << 3)) * 2;
    // B x4 pair p: matrices [nt=2p,k0-7],[nt=2p,k8-15],[nt=2p+1,k0-7],[nt=2p+1,k8-15]
    #pragma unroll
    for (int p = 0; p < 4; p++) {
        int n_off = p * 16 + ((lane >> 4) << 3) + (lane & 7);
        offB[p] = ((wn * 64 + n_off) * SBH + (((lane >> 3) & 1) << 3)) * 2;
    }

    float acc[4][8][4];
    #pragma unroll
    for (int i = 0; i < 4; i++)
        #pragma unroll
        for (int j = 0; j < 8; j++)
            #pragma unroll
            for (int r = 0; r < 4; r++) acc[i][j][r] = 0.f;

    // prologue: stages 0..2
    load_tile(0, 0); cp_commit();
    load_tile(1, 1); cp_commit();
    load_tile(2, 2); cp_commit();

    for (int kt = 0; kt < KT; kt++) {
        const int stage = kt & (NSTAGE - 1);
        cp_wait<2>();          // tile kt resident (2 newest groups may be pending)
        __syncthreads();

        const uint32_t sA = sb + (stage * SA_HALF) * 2;
        const uint32_t sB = sb + (NSTAGE * SA_HALF + stage * SB_HALF) * 2;

        #pragma unroll
        for (int ks = 0; ks < 2; ks++) {      // two k16 steps per 32-k tile
            const uint32_t kb = ks * 32;      // 16 halves = 32 bytes
            uint32_t af[4][4], bf[8][2];
            #pragma unroll
            for (int mt = 0; mt < 4; mt++)
                ldsm_x4(af[mt][0], af[mt][1], af[mt][2], af[mt][3],
                        sA + offA[mt] + kb);
            #pragma unroll
            for (int p = 0; p < 4; p++)
                ldsm_x4(bf[2*p][0], bf[2*p][1], bf[2*p+1][0], bf[2*p+1][1],
                        sB + offB[p] + kb);
            #pragma unroll
            for (int mt = 0; mt < 4; mt++)
                #pragma unroll
                for (int nt = 0; nt < 8; nt++) {
                    asm volatile(
                        "mma.sync.aligned.m16n8k16.row.col.f32.f16.f16.f32 "
                        "{%0,%1,%2,%3}, {%4,%5,%6,%7}, {%8,%9}, {%0,%1,%2,%3};\n"
                        : "+f"(acc[mt][nt][0]), "+f"(acc[mt][nt][1]),
                          "+f"(acc[mt][nt][2]), "+f"(acc[mt][nt][3])
                        : "r"(af[mt][0]), "r"(af[mt][1]), "r"(af[mt][2]), "r"(af[mt][3]),
                          "r"(bf[nt][0]), "r"(bf[nt][1]));
                }
        }

        if (kt + 3 < KT) load_tile(kt + 3, (kt + 3) & (NSTAGE - 1));
        cp_commit();           // commit every iter (possibly empty) -> stable wait counts
    }

    // epilogue
    #pragma unroll
    for (int mt = 0; mt < 4; mt++) {
        int r0 = rowBase + wm * 64 + mt * 16 + g;
        if (PHASE1) {
            __half* Ch = g_h + (size_t)e * CCAP * N;
            #pragma unroll
            for (int nt = 0; nt < 8; nt++) {
                int c0 = colBase + wn * 64 + nt * 8 + tg * 2;
                float b0 = __ldg(bias + c0), b1 = __ldg(bias + c0 + 1);
                __half2 h01 = __floats2half2_rn(gelu_tanh(acc[mt][nt][0] + b0),
                                                gelu_tanh(acc[mt][nt][1] + b1));
                __half2 h23 = __floats2half2_rn(gelu_tanh(acc[mt][nt][2] + b0),
                                                gelu_tanh(acc[mt][nt][3] + b1));
                *(__half2*)&Ch[(size_t)r0       * N + c0] = h01;
                *(__half2*)&Ch[(size_t)(r0 + 8) * N + c0] = h23;
            }
        } else {
            // fused combine: scatter gate * (acc + bias) to out[token]
            int tokA = g_slot_tok[e * CCAP + r0];
            int tokB = g_slot_tok[e * CCAP + r0 + 8];
            float gvA = (tokA >= 0) ? g_gate[tokA] : 0.f;
            float gvB = (tokB >= 0) ? g_gate[tokB] : 0.f;
            float* oA = outp + (size_t)tokA * ODIM;
            float* oB = outp + (size_t)tokB * ODIM;
            #pragma unroll
            for (int nt = 0; nt < 8; nt++) {
                int c0 = colBase + wn * 64 + nt * 8 + tg * 2;
                float b0 = __ldg(bias + c0), b1 = __ldg(bias + c0 + 1);
                if (tokA >= 0)
                    *(float2*)&oA[c0] = make_float2(gvA * (acc[mt][nt][0] + b0),
                                                    gvA * (acc[mt][nt][1] + b1));
                if (tokB >= 0)
                    *(float2*)&oB[c0] = make_float2(gvB * (acc[mt][nt][2] + b0),
                                                    gvB * (acc[mt][nt][3] + b1));
            }
        }
    }
}

// ---------------- 7. l_aux ----------------
__global__ void laux_kernel(float* __restrict__ out, int out_size) {
    __shared__ float sp[4][256];
    __shared__ float sc[4][256];
    int t = threadIdx.x;
    float p[4] = {0.f, 0.f, 0.f, 0.f};
    float c[4] = {0.f, 0.f, 0.f, 0.f};
    for (int s = t; s < S_TOK; s += 256) {
        float4 pr = ((const float4*)g_probs)[s];
        p[0] += pr.x; p[1] += pr.y; p[2] += pr.z; p[3] += pr.w;
        int e = g_eidx[s];
        #pragma unroll
        for (int k = 0; k < 4; k++) c[k] += (e == k) ? 1.f : 0.f;
    }
    #pragma unroll
    for (int k = 0; k < 4; k++) { sp[k][t] = p[k]; sc[k][t] = c[k]; }
    __syncthreads();
    for (int off = 128; off; off >>= 1) {
        if (t < off) {
            #pragma unroll
            for (int k = 0; k < 4; k++) {
                sp[k][t] += sp[k][t + off];
                sc[k][t] += sc[k][t + off];
            }
        }
        __syncthreads();
    }
    if (t == 0 && out_size > S_TOK * ODIM) {
        float inv = 1.0f / (float)S_TOK;
        float l = 0.f;
        #pragma unroll
        for (int k = 0; k < 4; k++) l += (sp[k][0] * inv) * (sc[k][0] * inv);
        out[(size_t)S_TOK * ODIM] = l * (float)EEXP;
    }
}

// ---------------- launch ----------------
extern "C" void kernel_launch(void* const* d_in, const int* in_sizes, int n_in,
                              void* d_out, int out_size) {
    (void)in_sizes; (void)n_in;
    const float* hs = (const float*)d_in[0];   // [8,1024,1024]
    const float* gw = (const float*)d_in[1];   // [1024,4]
    const float* w1 = (const float*)d_in[2];   // [4,1024,4096]
    const float* b1 = (const float*)d_in[3];   // [4,4096]
    const float* w2 = (const float*)d_in[4];   // [4,4096,1024]
    const float* b2 = (const float*)d_in[5];   // [4,1024]
    float* out = (float*)d_out;

    cudaFuncSetAttribute(moe_gemm<true>,
                         cudaFuncAttributeMaxDynamicSharedMemorySize, SMEM_BYTES);
    cudaFuncSetAttribute(moe_gemm<false>,
                         cudaFuncAttributeMaxDynamicSharedMemorySize, SMEM_BYTES);

    __half* w1t; cudaGetSymbolAddress((void**)&w1t, g_w1t);
    __half* w2t; cudaGetSymbolAddress((void**)&w2t, g_w2t);

    gate_kernel<<<S_TOK / 8, 256>>>(hs, gw);
    scan_kernel<<<1, 1024>>>();
    gather_kernel<<<EEXP * CCAP, 256>>>(hs);
    zero_dropped<<<S_TOK / 8, 256>>>(out);
    transpose_kernel<<<dim3(HDIM / 64, MDIM / 64, EEXP), 256>>>(w1, w1t, MDIM, HDIM);
    transpose_kernel<<<dim3(ODIM / 64, HDIM / 64, EEXP), 256>>>(w2, w2t, HDIM, ODIM);
    moe_gemm<true ><<<dim3(HDIM / GBN, CCAP / GBM, EEXP), 128, SMEM_BYTES>>>(w1t, b1, out);
    moe_gemm<false><<<dim3(ODIM / GBN, CCAP / GBM, EEXP), 128, SMEM_BYTES>>>(w2t, b2, out);
    laux_kernel<<<1, 256>>>(out, out_size);
}